// round 10
// baseline (speedup 1.0000x reference)
#include <cuda_runtime.h>
#include <cuda_fp16.h>
#include <math.h>
#include <stdint.h>

#define NE   64
#define TK   8
#define DIM  2048
#define TM   64             // tokens per CTA
#define KC   64             // fp32 k per chunk
#define NCH  (DIM / KC)     // 32 chunks
#define SW   36             // smem row stride in words (32 data + 4 pad)
#define NTH  256
#define INV2048 (1.0f / 2048.0f)

// plane offsets per stage (words); rows are 64 halves = 32 words (+4 pad)
#define APL (TM * SW)            // 2304
#define BPL (NE * SW)            // 2304
#define AH_O 0
#define AL_O APL
#define BH_O (2 * APL)
#define BL_O (2 * APL + BPL)
#define STG_W (2 * APL + 2 * BPL)     // 9216 words = 36864 B
#define DYN_BYTES (2 * STG_W * 4)     // 73728 B
#define LS_STRIDE 68

__device__ __align__(16) uint16_t g_wh16[NE * DIM];   // W hi (fp16)
__device__ __align__(16) uint16_t g_wl16[NE * DIM];   // W lo (fp16, scaled 2^11)
__device__ __align__(16) float g_bias[NE];
__device__ float g_nbs;
__device__ float g_acc[NE];
__device__ unsigned int g_done;   // zero-init; reset by last CTA each run

// 2-term fp16 split of a float4 (lo scaled by 2^11)
static __device__ __forceinline__ void split2h(float4 v,
    uint32_t& h01, uint32_t& h23, uint32_t& l01, uint32_t& l23)
{
    __half2 a = __floats2half2_rn(v.x, v.y);
    __half2 b = __floats2half2_rn(v.z, v.w);
    float rx = v.x - __half2float(__low2half(a));
    float ry = v.y - __half2float(__high2half(a));
    float rz = v.z - __half2float(__low2half(b));
    float rw = v.w - __half2float(__high2half(b));
    __half2 la = __floats2half2_rn(rx * 2048.f, ry * 2048.f);
    __half2 lb = __floats2half2_rn(rz * 2048.f, rw * 2048.f);
    h01 = *(uint32_t*)&a;  h23 = *(uint32_t*)&b;
    l01 = *(uint32_t*)&la; l23 = *(uint32_t*)&lb;
}

static __device__ __forceinline__ void mma16f(float* c,
    uint32_t a0, uint32_t a1, uint32_t a2, uint32_t a3, uint32_t b0, uint32_t b1)
{
    asm volatile(
        "mma.sync.aligned.m16n8k16.row.col.f32.f16.f16.f32 "
        "{%0,%1,%2,%3}, {%4,%5,%6,%7}, {%8,%9}, {%0,%1,%2,%3};"
        : "+f"(c[0]), "+f"(c[1]), "+f"(c[2]), "+f"(c[3])
        : "r"(a0), "r"(a1), "r"(a2), "r"(a3), "r"(b0), "r"(b1));
}

static __device__ __forceinline__ void ldsm4(uint32_t& r0, uint32_t& r1,
                                             uint32_t& r2, uint32_t& r3, uint32_t a)
{
    asm volatile("ldmatrix.sync.aligned.m8n8.x4.shared.b16 {%0,%1,%2,%3}, [%4];"
                 : "=r"(r0), "=r"(r1), "=r"(r2), "=r"(r3) : "r"(a));
}

static __device__ __forceinline__ void cpa16(uint32_t dst, const void* src) {
    asm volatile("cp.async.ca.shared.global [%0], [%1], 16;"
                 :: "r"(dst), "l"(src) : "memory");
}

// ---------------------------------------------------------------------------
// Setup: split W into fp16 hi/lo planes (blocks 0..63), bias (block 64)
// ---------------------------------------------------------------------------
__global__ void k_setup(const float* __restrict__ W,
                        const float* __restrict__ loads,
                        const float* __restrict__ bs)
{
    int b = blockIdx.x, tid = threadIdx.x;

    if (b < NE) {
        const float4* wr = (const float4*)(W + (size_t)b * DIM);
        uint32_t* wh = (uint32_t*)g_wh16;
        uint32_t* wl = (uint32_t*)g_wl16;
        #pragma unroll
        for (int u = 0; u < 2; u++) {
            int f = u * 256 + tid;
            uint32_t h01, h23, l01, l23;
            split2h(wr[f], h01, h23, l01, l23);
            int idx = (b * DIM + f * 4) >> 1;
            wh[idx] = h01; wh[idx + 1] = h23;
            wl[idx] = l01; wl[idx + 1] = l23;
        }
    } else {
        __shared__ float s[NE], s2[NE];
        if (tid < NE) s[tid] = loads[tid];
        __syncthreads();
        float sum = 0.f, q = 0.f;
        const float t = 1.0f / (float)NE;
        if (tid < NE) {
            #pragma unroll
            for (int i = 0; i < NE; i++) sum += s[i];
            sum = fmaxf(sum, 1e-8f);
            q = s[tid] / sum;
            s2[tid] = t * (logf(t) - logf(fmaxf(q, 1e-8f)));
        }
        __syncthreads();
        if (tid < NE) {
            float kl = 0.f;
            #pragma unroll
            for (int i = 0; i < NE; i++) kl += s2[i];
            float adaptive = 1.0f / (1.0f + expf(-10.0f * kl));
            float nbs = 0.9f * bs[0] + 0.1f * adaptive;
            g_bias[tid] = tanhf((q - t) * (float)NE) * nbs;
            g_acc[tid] = 0.f;
            if (tid == 0) g_nbs = nbs;
        }
    }
}

// ---------------------------------------------------------------------------
// Router: fp16 2-term / 3-product mma16 GEMM, TM=64, 2 CTAs/SM
// warp w (0..7): h = w&1 token half (32 tok), e2 = (w>>1)&1 expert half, ksw = w>>2
// ---------------------------------------------------------------------------
__global__ __launch_bounds__(NTH, 2) void k_router(
    const float* __restrict__ X,      // [ntok, DIM]
    const float* __restrict__ noise,  // [ntok, NE]
    const float* __restrict__ loads,  // [NE]
    float* __restrict__ out,
    int ntok)
{
    extern __shared__ __align__(16) float smem[];
    __shared__ float sLoads[NE];
    __shared__ float sBias[NE];
    __shared__ int sLast;

    const int tid  = threadIdx.x;
    const int lane = tid & 31;
    const int warp = tid >> 5;
    const int h    = warp & 1;
    const int e2   = (warp >> 1) & 1;
    const int ksw  = warp >> 2;
    const int g    = lane >> 2;
    const int tig  = lane & 3;
    const int t0   = blockIdx.x * TM;

    if (tid < NE) { sLoads[tid] = 0.f; sBias[tid] = g_bias[tid]; }

    const uint32_t smem32 = (uint32_t)__cvta_generic_to_shared(smem);

    // hoisted per-lane ldmatrix word offsets (within stage)
    const uint32_t aWord = (uint32_t)((32 * h + (lane & 15)) * SW
                                      + ksw * 16 + ((lane >> 4) << 2));
    const uint32_t bWord = (uint32_t)(BH_O
                                      + (32 * e2 + ((lane >> 4) << 3) + (lane & 7)) * SW
                                      + ksw * 16 + (((lane >> 3) & 1) << 2));

    // fill indices: X -> 16 fp32 per thread (quarter row)
    const int ft = tid >> 2;   // X token 0..63
    const int fq = tid & 3;    // k quarter (16 fp32)

    float acc0[2][4][4], accS[2][4][4];
    #pragma unroll
    for (int i = 0; i < 2; i++)
        #pragma unroll
        for (int j = 0; j < 4; j++)
            #pragma unroll
            for (int q = 0; q < 4; q++) { acc0[i][j][q] = 0.f; accS[i][j][q] = 0.f; }

    float4 xr[4];

    // ---- fill chunk 0 into stage 0 ----
    {
        uint32_t* sw = (uint32_t*)smem;
        const float* xp = X + (size_t)(t0 + ft) * DIM + fq * 16;
        int wb = ft * SW + fq * 8;
        #pragma unroll
        for (int u = 0; u < 4; u++) {
            float4 v = *(const float4*)(xp + u * 4);
            uint32_t h01, h23, l01, l23;
            split2h(v, h01, h23, l01, l23);
            *(uint2*)&sw[AH_O + wb + u * 2] = make_uint2(h01, h23);
            *(uint2*)&sw[AL_O + wb + u * 2] = make_uint2(l01, l23);
        }
        #pragma unroll
        for (int u = 0; u < 2; u++) {
            int f = u * NTH + tid;
            int e = f >> 3, q = f & 7;
            uint32_t bw = (uint32_t)(e * SW * 4 + q * 16);
            cpa16(smem32 + BH_O * 4 + bw, g_wh16 + (size_t)e * DIM + q * 8);
            cpa16(smem32 + BL_O * 4 + bw, g_wl16 + (size_t)e * DIM + q * 8);
        }
        asm volatile("cp.async.commit_group;" ::: "memory");
        asm volatile("cp.async.wait_group 0;" ::: "memory");
    }
    __syncthreads();

    // ---- mainloop ----
    for (int c = 0; c < NCH; ++c) {
        const bool more = (c + 1 < NCH);
        if (more) {
            int kb = (c + 1) * KC;
            const float* xp = X + (size_t)(t0 + ft) * DIM + kb + fq * 16;
            #pragma unroll
            for (int u = 0; u < 4; u++) xr[u] = *(const float4*)(xp + u * 4);
            uint32_t sb = smem32 + (uint32_t)(((c + 1) & 1) * STG_W * 4);
            #pragma unroll
            for (int u = 0; u < 2; u++) {
                int f = u * NTH + tid;
                int e = f >> 3, q = f & 7;
                uint32_t bw = (uint32_t)(e * SW * 4 + q * 16);
                cpa16(sb + BH_O * 4 + bw, g_wh16 + (size_t)e * DIM + kb + q * 8);
                cpa16(sb + BL_O * 4 + bw, g_wl16 + (size_t)e * DIM + kb + q * 8);
            }
            asm volatile("cp.async.commit_group;" ::: "memory");
        }

        // ---- consume stage c&1 (ldmatrix fragments) ----
        {
            const uint32_t stg32 = smem32 + (uint32_t)((c & 1) * STG_W * 4);
            const uint32_t aA = stg32 + aWord * 4;
            const uint32_t bA = stg32 + bWord * 4;

            #pragma unroll
            for (int kk = 0; kk < 2; kk++) {
                uint32_t Ah[2][4], Al[2][4];
                #pragma unroll
                for (int i = 0; i < 2; i++) {
                    uint32_t a = aA + (uint32_t)(i * 16 * SW * 4 + kk * 32);
                    ldsm4(Ah[i][0], Ah[i][1], Ah[i][2], Ah[i][3], a);
                    ldsm4(Al[i][0], Al[i][1], Al[i][2], Al[i][3], a + APL * 4);
                }
                #pragma unroll
                for (int jp = 0; jp < 2; jp++) {
                    uint32_t b = bA + (uint32_t)(jp * 16 * SW * 4 + kk * 32);
                    uint32_t Bh0, Bh1, Bh2, Bh3, Bl0, Bl1, Bl2, Bl3;
                    ldsm4(Bh0, Bh1, Bh2, Bh3, b);
                    ldsm4(Bl0, Bl1, Bl2, Bl3, b + (BL_O - BH_O) * 4);
                    #pragma unroll
                    for (int i = 0; i < 2; i++) {
                        mma16f(acc0[i][2*jp],   Ah[i][0], Ah[i][1], Ah[i][2], Ah[i][3], Bh0, Bh1);
                        mma16f(accS[i][2*jp],   Ah[i][0], Ah[i][1], Ah[i][2], Ah[i][3], Bl0, Bl1);
                        mma16f(accS[i][2*jp],   Al[i][0], Al[i][1], Al[i][2], Al[i][3], Bh0, Bh1);
                        mma16f(acc0[i][2*jp+1], Ah[i][0], Ah[i][1], Ah[i][2], Ah[i][3], Bh2, Bh3);
                        mma16f(accS[i][2*jp+1], Ah[i][0], Ah[i][1], Ah[i][2], Ah[i][3], Bl2, Bl3);
                        mma16f(accS[i][2*jp+1], Al[i][0], Al[i][1], Al[i][2], Al[i][3], Bh2, Bh3);
                    }
                }
            }
        }

        // ---- store X(c+1) + drain B cp.async ----
        if (more) {
            uint32_t* sw = (uint32_t*)((char*)smem + ((c + 1) & 1) * STG_W * 4);
            int wb = ft * SW + fq * 8;
            #pragma unroll
            for (int u = 0; u < 4; u++) {
                uint32_t h01, h23, l01, l23;
                split2h(xr[u], h01, h23, l01, l23);
                *(uint2*)&sw[AH_O + wb + u * 2] = make_uint2(h01, h23);
                *(uint2*)&sw[AL_O + wb + u * 2] = make_uint2(l01, l23);
            }
            asm volatile("cp.async.wait_group 0;" ::: "memory");
        }
        __syncthreads();
    }

    // ---- cross-kstep reduction into logits tile Ls[64][68] ----
    float* Ls = smem;
    for (int idx = tid; idx < TM * LS_STRIDE; idx += NTH) Ls[idx] = 0.f;
    __syncthreads();

    for (int round = 0; round < 2; round++) {
        if (ksw == round) {
            #pragma unroll
            for (int i = 0; i < 2; i++) {
                int rt = 32 * h + 16 * i + g;
                #pragma unroll
                for (int j = 0; j < 4; j++) {
                    int cc = 32 * e2 + 8 * j + 2 * tig;
                    Ls[rt * LS_STRIDE + cc]           += acc0[i][j][0] + accS[i][j][0] * INV2048;
                    Ls[rt * LS_STRIDE + cc + 1]       += acc0[i][j][1] + accS[i][j][1] * INV2048;
                    Ls[(rt + 8) * LS_STRIDE + cc]     += acc0[i][j][2] + accS[i][j][2] * INV2048;
                    Ls[(rt + 8) * LS_STRIDE + cc + 1] += acc0[i][j][3] + accS[i][j][3] * INV2048;
                }
            }
        }
        __syncthreads();
    }

    // ---- epilogue: per-token top-8 + softmax + load scatter ----
    if (tid < TM) {
        const int t = tid;
        size_t gt = (size_t)(t0 + t);

        float nzf[NE];
        const float4* nr = (const float4*)(noise + gt * NE);
        #pragma unroll
        for (int i = 0; i < 16; i++) {
            float4 v = nr[i];
            nzf[4 * i + 0] = v.x; nzf[4 * i + 1] = v.y;
            nzf[4 * i + 2] = v.z; nzf[4 * i + 3] = v.w;
        }

        float tv[TK];
        int   ti_[TK];
        #pragma unroll
        for (int k = 0; k < TK; k++) { tv[k] = -INFINITY; ti_[k] = -1; }

        for (int e = 0; e < NE; e++) {
            float v = Ls[t * LS_STRIDE + e] + 0.01f * nzf[e] - sBias[e];
            if (v > tv[TK - 1]) {                 // strict >: earlier equal value stays
                int p = TK - 1;
                while (p > 0 && tv[p - 1] < v) {  // stop at equal -> stable insert
                    tv[p] = tv[p - 1];
                    ti_[p] = ti_[p - 1];
                    --p;
                }
                tv[p] = v;
                ti_[p] = e;
            }
        }

        float m = tv[0];
        float w[TK];
        float ssum = 0.f;
        #pragma unroll
        for (int k = 0; k < TK; k++) { w[k] = expf(tv[k] - m); ssum += w[k]; }
        float inv = 1.0f / ssum;

        size_t woff = (size_t)ntok * TK;
        #pragma unroll
        for (int k = 0; k < TK; k++) {
            float wk = w[k] * inv;
            out[gt * TK + k]        = (float)ti_[k];
            out[woff + gt * TK + k] = wk;
            atomicAdd(&sLoads[ti_[k]], wk);
        }
    }
    __syncthreads();
    if (tid < NE) atomicAdd(&g_acc[tid], sLoads[tid]);

    // ---- fused finalize: last CTA writes EMA + bias strength ----
    __threadfence();
    __syncthreads();
    if (tid == 0) {
        unsigned int n = atomicAdd(&g_done, 1u);
        sLast = (n == gridDim.x - 1) ? 1 : 0;
    }
    __syncthreads();
    if (sLast && tid < NE) {
        float batch = atomicAdd(&g_acc[tid], 0.0f) / (float)ntok;
        size_t bofs = (size_t)ntok * TK * 2;
        out[bofs + tid] = 0.999f * loads[tid] + (1.0f - 0.999f) * batch;
        if (tid == 0) { out[bofs + NE] = g_nbs; g_done = 0u; }
    }
}

// ---------------------------------------------------------------------------
// Launch
// ---------------------------------------------------------------------------
extern "C" void kernel_launch(void* const* d_in, const int* in_sizes, int n_in,
                              void* d_out, int out_size)
{
    const float* X     = (const float*)d_in[0];  // hidden_states [4,4096,2048]
    const float* W     = (const float*)d_in[1];  // router_w [64,2048]
    const float* loads = (const float*)d_in[2];  // expert_loads [64]
    const float* bs    = (const float*)d_in[3];  // bias_strength [1]
    const float* noise = (const float*)d_in[4];  // noise [16384,64]
    float* out = (float*)d_out;

    int ntok = in_sizes[0] / DIM;

    cudaFuncSetAttribute(k_router, cudaFuncAttributeMaxDynamicSharedMemorySize, DYN_BYTES);

    k_setup<<<NE + 1, 256>>>(W, loads, bs);
    k_router<<<ntok / TM, NTH, DYN_BYTES>>>(X, noise, loads, out, ntok);
}

// round 11
// speedup vs baseline: 1.1385x; 1.1385x over previous
#include <cuda_runtime.h>
#include <cuda_fp16.h>
#include <math.h>
#include <stdint.h>

#define NE   64
#define TK   8
#define DIM  2048
#define TM   128            // tokens per CTA
#define NSTEP 64            // k16-steps per warp (2048/16/2 ksw-slices)
#define NTH  256
#define INV2048 (1.0f / 2048.0f)
#define LS_STRIDE 68

__device__ __align__(16) uint16_t g_wh16[NE * DIM];   // W hi (fp16)
__device__ __align__(16) uint16_t g_wl16[NE * DIM];   // W lo (fp16, scaled 2^11)
__device__ __align__(16) float g_bias[NE];
__device__ float g_nbs;
__device__ float g_acc[NE];
__device__ unsigned int g_done;   // zero-init; reset by last CTA each run

// 2-term fp16 split of a float2 (lo scaled by 2^11) -> packed fp16x2
static __device__ __forceinline__ void split2(float x, float y,
                                              uint32_t& hh, uint32_t& ll)
{
    __half2 a = __floats2half2_rn(x, y);       // low = x, high = y
    float rx = (x - __half2float(__low2half(a))) * 2048.f;
    float ry = (y - __half2float(__high2half(a))) * 2048.f;
    __half2 l = __floats2half2_rn(rx, ry);
    hh = *(uint32_t*)&a;
    ll = *(uint32_t*)&l;
}

static __device__ __forceinline__ void mma16f(float* c,
    uint32_t a0, uint32_t a1, uint32_t a2, uint32_t a3, uint32_t b0, uint32_t b1)
{
    asm volatile(
        "mma.sync.aligned.m16n8k16.row.col.f32.f16.f16.f32 "
        "{%0,%1,%2,%3}, {%4,%5,%6,%7}, {%8,%9}, {%0,%1,%2,%3};"
        : "+f"(c[0]), "+f"(c[1]), "+f"(c[2]), "+f"(c[3])
        : "r"(a0), "r"(a1), "r"(a2), "r"(a3), "r"(b0), "r"(b1));
}

// ---------------------------------------------------------------------------
// Setup: split W into fp16 hi/lo planes (blocks 0..63), bias (block 64)
// ---------------------------------------------------------------------------
__global__ void k_setup(const float* __restrict__ W,
                        const float* __restrict__ loads,
                        const float* __restrict__ bs)
{
    int b = blockIdx.x, tid = threadIdx.x;

    if (b < NE) {
        const float2* wr = (const float2*)(W + (size_t)b * DIM);
        uint32_t* wh = (uint32_t*)g_wh16;
        uint32_t* wl = (uint32_t*)g_wl16;
        #pragma unroll
        for (int u = 0; u < 4; u++) {
            int f = u * 256 + tid;
            float2 v = wr[f];
            uint32_t hh, ll;
            split2(v.x, v.y, hh, ll);
            int idx = b * (DIM / 2) + f;
            wh[idx] = hh;
            wl[idx] = ll;
        }
    } else {
        __shared__ float s[NE], s2[NE];
        if (tid < NE) s[tid] = loads[tid];
        __syncthreads();
        float sum = 0.f, q = 0.f;
        const float t = 1.0f / (float)NE;
        if (tid < NE) {
            #pragma unroll
            for (int i = 0; i < NE; i++) sum += s[i];
            sum = fmaxf(sum, 1e-8f);
            q = s[tid] / sum;
            s2[tid] = t * (logf(t) - logf(fmaxf(q, 1e-8f)));
        }
        __syncthreads();
        if (tid < NE) {
            float kl = 0.f;
            #pragma unroll
            for (int i = 0; i < NE; i++) kl += s2[i];
            float adaptive = 1.0f / (1.0f + expf(-10.0f * kl));
            float nbs = 0.9f * bs[0] + 0.1f * adaptive;
            g_bias[tid] = tanhf((q - t) * (float)NE) * nbs;
            g_acc[tid] = 0.f;
            if (tid == 0) g_nbs = nbs;
        }
    }
}

// ---------------------------------------------------------------------------
// Router: smem-free mainloop — operands LDG'd directly in fragment layout.
// warp w (0..7): h = w&1 token half, e2 = (w>>1)&1 expert half, ksw = w>>2
// ---------------------------------------------------------------------------
__global__ __launch_bounds__(NTH, 1) void k_router(
    const float* __restrict__ X,      // [ntok, DIM]
    const float* __restrict__ noise,  // [ntok, NE]
    const float* __restrict__ loads,  // [NE]
    float* __restrict__ out,
    int ntok)
{
    __shared__ float Ls[TM * LS_STRIDE];    // epilogue logits tile (34816 B)
    __shared__ float sLoads[NE];
    __shared__ float sBias[NE];
    __shared__ int sLast;

    const int tid  = threadIdx.x;
    const int lane = tid & 31;
    const int warp = tid >> 5;
    const int h    = warp & 1;
    const int e2   = (warp >> 1) & 1;
    const int ksw  = warp >> 2;       // 0/1: which k16 of each 32-wide slice
    const int g    = lane >> 2;
    const int tig  = lane & 3;
    const int t0   = blockIdx.x * TM;

    if (tid < NE) { sLoads[tid] = 0.f; sBias[tid] = g_bias[tid]; }

    // per-lane base pointers (fragment layout direct from global)
    const float* xb = X + (size_t)(t0 + 64 * h + g) * DIM + 2 * tig + 16 * ksw;
    const uint32_t* whp = (const uint32_t*)g_wh16 + (32 * e2 + g) * (DIM / 2) + tig + 8 * ksw;
    const uint32_t* wlp = (const uint32_t*)g_wl16 + (32 * e2 + g) * (DIM / 2) + tig + 8 * ksw;

    float acc0[4][4][4], accS[4][4][4];
    #pragma unroll
    for (int i = 0; i < 4; i++)
        #pragma unroll
        for (int j = 0; j < 4; j++)
            #pragma unroll
            for (int q = 0; q < 4; q++) { acc0[i][j][q] = 0.f; accS[i][j][q] = 0.f; }

    // ---- mainloop: 64 independent steps, no smem, no barriers ----
    #pragma unroll 2
    for (int s = 0; s < NSTEP; ++s) {
        const int k = s * 32;             // fp32 offset of this step (lane adds ksw*16)
        const int kw = s * 16;            // word offset in fp16 planes

        // A raw loads: 4 token tiles x 4 fragment positions (float2 each)
        float2 ar[4][4];
        #pragma unroll
        for (int i = 0; i < 4; i++) {
            const float* p = xb + (size_t)i * 16 * DIM + k;
            ar[i][0] = *(const float2*)(p);
            ar[i][1] = *(const float2*)(p + 8 * DIM);
            ar[i][2] = *(const float2*)(p + 8);
            ar[i][3] = *(const float2*)(p + 8 * DIM + 8);
        }
        // B loads: 4 expert tiles x {b0,b1} hi + lo (pre-split fp16x2 words)
        uint32_t Bh[4][2], Bl[4][2];
        #pragma unroll
        for (int j = 0; j < 4; j++) {
            const uint32_t* qh = whp + j * 8 * (DIM / 2) + kw;
            const uint32_t* ql = wlp + j * 8 * (DIM / 2) + kw;
            Bh[j][0] = qh[0]; Bh[j][1] = qh[4];
            Bl[j][0] = ql[0]; Bl[j][1] = ql[4];
        }

        // register split of A
        uint32_t Ah[4][4], Al[4][4];
        #pragma unroll
        for (int i = 0; i < 4; i++)
            #pragma unroll
            for (int r = 0; r < 4; r++)
                split2(ar[i][r].x, ar[i][r].y, Ah[i][r], Al[i][r]);

        // 3 product groups; no back-to-back same-accumulator RAW
        #pragma unroll
        for (int i = 0; i < 4; i++)
            #pragma unroll
            for (int j = 0; j < 4; j++)
                mma16f(acc0[i][j], Ah[i][0], Ah[i][1], Ah[i][2], Ah[i][3], Bh[j][0], Bh[j][1]);
        #pragma unroll
        for (int i = 0; i < 4; i++)
            #pragma unroll
            for (int j = 0; j < 4; j++)
                mma16f(accS[i][j], Ah[i][0], Ah[i][1], Ah[i][2], Ah[i][3], Bl[j][0], Bl[j][1]);
        #pragma unroll
        for (int i = 0; i < 4; i++)
            #pragma unroll
            for (int j = 0; j < 4; j++)
                mma16f(accS[i][j], Al[i][0], Al[i][1], Al[i][2], Al[i][3], Bh[j][0], Bh[j][1]);
    }

    // ---- reduction across ksw pairs into logits tile ----
    __syncthreads();
    for (int idx = tid; idx < TM * LS_STRIDE; idx += NTH) Ls[idx] = 0.f;
    __syncthreads();

    for (int round = 0; round < 2; round++) {
        if (ksw == round) {
            #pragma unroll
            for (int i = 0; i < 4; i++) {
                int rt = 64 * h + 16 * i + g;
                #pragma unroll
                for (int j = 0; j < 4; j++) {
                    int cc = 32 * e2 + 8 * j + 2 * tig;
                    Ls[rt * LS_STRIDE + cc]           += acc0[i][j][0] + accS[i][j][0] * INV2048;
                    Ls[rt * LS_STRIDE + cc + 1]       += acc0[i][j][1] + accS[i][j][1] * INV2048;
                    Ls[(rt + 8) * LS_STRIDE + cc]     += acc0[i][j][2] + accS[i][j][2] * INV2048;
                    Ls[(rt + 8) * LS_STRIDE + cc + 1] += acc0[i][j][3] + accS[i][j][3] * INV2048;
                }
            }
        }
        __syncthreads();
    }

    // ---- epilogue: per-token top-8 + softmax + load scatter ----
    if (tid < TM) {
        const int t = tid;
        size_t gt = (size_t)(t0 + t);

        float nzf[NE];
        const float4* nr = (const float4*)(noise + gt * NE);
        #pragma unroll
        for (int i = 0; i < 16; i++) {
            float4 v = nr[i];
            nzf[4 * i + 0] = v.x; nzf[4 * i + 1] = v.y;
            nzf[4 * i + 2] = v.z; nzf[4 * i + 3] = v.w;
        }

        float tv[TK];
        int   ti_[TK];
        #pragma unroll
        for (int k = 0; k < TK; k++) { tv[k] = -INFINITY; ti_[k] = -1; }

        for (int e = 0; e < NE; e++) {
            float v = Ls[t * LS_STRIDE + e] + 0.01f * nzf[e] - sBias[e];
            if (v > tv[TK - 1]) {                 // strict >: earlier equal value stays
                int p = TK - 1;
                while (p > 0 && tv[p - 1] < v) {  // stop at equal -> stable insert
                    tv[p] = tv[p - 1];
                    ti_[p] = ti_[p - 1];
                    --p;
                }
                tv[p] = v;
                ti_[p] = e;
            }
        }

        float m = tv[0];
        float w[TK];
        float ssum = 0.f;
        #pragma unroll
        for (int k = 0; k < TK; k++) { w[k] = expf(tv[k] - m); ssum += w[k]; }
        float inv = 1.0f / ssum;

        size_t woff = (size_t)ntok * TK;
        #pragma unroll
        for (int k = 0; k < TK; k++) {
            float wk = w[k] * inv;
            out[gt * TK + k]        = (float)ti_[k];
            out[woff + gt * TK + k] = wk;
            atomicAdd(&sLoads[ti_[k]], wk);
        }
    }
    __syncthreads();
    if (tid < NE) atomicAdd(&g_acc[tid], sLoads[tid]);

    // ---- fused finalize: last CTA writes EMA + bias strength ----
    __threadfence();
    __syncthreads();
    if (tid == 0) {
        unsigned int n = atomicAdd(&g_done, 1u);
        sLast = (n == gridDim.x - 1) ? 1 : 0;
    }
    __syncthreads();
    if (sLast && tid < NE) {
        float batch = atomicAdd(&g_acc[tid], 0.0f) / (float)ntok;
        size_t bofs = (size_t)ntok * TK * 2;
        out[bofs + tid] = 0.999f * loads[tid] + (1.0f - 0.999f) * batch;
        if (tid == 0) { out[bofs + NE] = g_nbs; g_done = 0u; }
    }
}

// ---------------------------------------------------------------------------
// Launch
// ---------------------------------------------------------------------------
extern "C" void kernel_launch(void* const* d_in, const int* in_sizes, int n_in,
                              void* d_out, int out_size)
{
    const float* X     = (const float*)d_in[0];  // hidden_states [4,4096,2048]
    const float* W     = (const float*)d_in[1];  // router_w [64,2048]
    const float* loads = (const float*)d_in[2];  // expert_loads [64]
    const float* bs    = (const float*)d_in[3];  // bias_strength [1]
    const float* noise = (const float*)d_in[4];  // noise [16384,64]
    float* out = (float*)d_out;

    int ntok = in_sizes[0] / DIM;

    k_setup<<<NE + 1, 256>>>(W, loads, bs);
    k_router<<<ntok / TM, NTH>>>(X, noise, loads, out, ntok);
}

// round 12
// speedup vs baseline: 1.7739x; 1.5581x over previous
#include <cuda_runtime.h>
#include <cuda_fp16.h>
#include <math.h>
#include <stdint.h>

#define NE   64
#define TK   8
#define DIM  2048
#define TM   128            // tokens per CTA
#define KC   64             // fp32 k per chunk (64 fp16 = 128B row)
#define NCH  (DIM / KC)     // 32 chunks
#define NTH  256
#define INV2048 (1.0f / 2048.0f)
#define LS_STRIDE 68

// stage byte layout: 128B rows, XOR-swizzled 16B chunks
#define AH_B 0
#define AL_B 16384
#define BH_B 32768
#define BL_B 40960
#define STG_B 49152
#define DYN_BYTES (2 * STG_B)    // 98304

__device__ __align__(16) uint16_t g_wh16[NE * DIM];   // W hi (fp16)
__device__ __align__(16) uint16_t g_wl16[NE * DIM];   // W lo (fp16, scaled 2^11)
__device__ __align__(16) float g_bias[NE];
__device__ float g_nbs;
__device__ float g_acc[NE];
__device__ unsigned int g_done;   // zero-init; reset by last CTA each run

// swizzled byte offset of 16B chunk (row, c) within a plane
#define SWZ(row, c) (((row) << 7) + ((((c) ^ ((row) & 7))) << 4))

// 2-term fp16 split of (x,y) -> packed hi fp16x2, lo fp16x2 (lo scaled 2^11)
static __device__ __forceinline__ void split2(float x, float y,
                                              uint32_t& hh, uint32_t& ll)
{
    __half2 a = __floats2half2_rn(x, y);
    float rx = (x - __half2float(__low2half(a))) * 2048.f;
    float ry = (y - __half2float(__high2half(a))) * 2048.f;
    __half2 l = __floats2half2_rn(rx, ry);
    hh = *(uint32_t*)&a;
    ll = *(uint32_t*)&l;
}

static __device__ __forceinline__ void mma16f(float* c,
    uint32_t a0, uint32_t a1, uint32_t a2, uint32_t a3, uint32_t b0, uint32_t b1)
{
    asm volatile(
        "mma.sync.aligned.m16n8k16.row.col.f32.f16.f16.f32 "
        "{%0,%1,%2,%3}, {%4,%5,%6,%7}, {%8,%9}, {%0,%1,%2,%3};"
        : "+f"(c[0]), "+f"(c[1]), "+f"(c[2]), "+f"(c[3])
        : "r"(a0), "r"(a1), "r"(a2), "r"(a3), "r"(b0), "r"(b1));
}

static __device__ __forceinline__ void ldsm4(uint32_t& r0, uint32_t& r1,
                                             uint32_t& r2, uint32_t& r3, uint32_t a)
{
    asm volatile("ldmatrix.sync.aligned.m8n8.x4.shared.b16 {%0,%1,%2,%3}, [%4];"
                 : "=r"(r0), "=r"(r1), "=r"(r2), "=r"(r3) : "r"(a));
}

static __device__ __forceinline__ void cpa16(uint32_t dst, const void* src) {
    asm volatile("cp.async.ca.shared.global [%0], [%1], 16;"
                 :: "r"(dst), "l"(src) : "memory");
}

// ---------------------------------------------------------------------------
// Setup: split W into fp16 hi/lo planes (blocks 0..63), bias (block 64)
// ---------------------------------------------------------------------------
__global__ void k_setup(const float* __restrict__ W,
                        const float* __restrict__ loads,
                        const float* __restrict__ bs)
{
    int b = blockIdx.x, tid = threadIdx.x;

    if (b < NE) {
        const float2* wr = (const float2*)(W + (size_t)b * DIM);
        uint32_t* wh = (uint32_t*)g_wh16;
        uint32_t* wl = (uint32_t*)g_wl16;
        #pragma unroll
        for (int u = 0; u < 4; u++) {
            int f = u * 256 + tid;
            float2 v = wr[f];
            uint32_t hh, ll;
            split2(v.x, v.y, hh, ll);
            int idx = b * (DIM / 2) + f;
            wh[idx] = hh;
            wl[idx] = ll;
        }
    } else {
        __shared__ float s[NE], s2[NE];
        if (tid < NE) s[tid] = loads[tid];
        __syncthreads();
        float sum = 0.f, q = 0.f;
        const float t = 1.0f / (float)NE;
        if (tid < NE) {
            #pragma unroll
            for (int i = 0; i < NE; i++) sum += s[i];
            sum = fmaxf(sum, 1e-8f);
            q = s[tid] / sum;
            s2[tid] = t * (logf(t) - logf(fmaxf(q, 1e-8f)));
        }
        __syncthreads();
        if (tid < NE) {
            float kl = 0.f;
            #pragma unroll
            for (int i = 0; i < NE; i++) kl += s2[i];
            float adaptive = 1.0f / (1.0f + expf(-10.0f * kl));
            float nbs = 0.9f * bs[0] + 0.1f * adaptive;
            g_bias[tid] = tanhf((q - t) * (float)NE) * nbs;
            g_acc[tid] = 0.f;
            if (tid == 0) g_nbs = nbs;
        }
    }
}

// ---------------------------------------------------------------------------
// Router: fp16 2-term / 3-product mma16 GEMM, swizzled 128B-row staging
// warp w (0..7): h = w&1 token half, e2 = (w>>1)&1 expert half, ksw = w>>2
// ---------------------------------------------------------------------------
__global__ __launch_bounds__(NTH, 1) void k_router(
    const float* __restrict__ X,      // [ntok, DIM]
    const float* __restrict__ noise,  // [ntok, NE]
    const float* __restrict__ loads,  // [NE]
    float* __restrict__ out,
    int ntok)
{
    extern __shared__ __align__(16) char dsm[];
    __shared__ float sLoads[NE];
    __shared__ float sBias[NE];
    __shared__ int sLast;

    const int tid  = threadIdx.x;
    const int lane = tid & 31;
    const int warp = tid >> 5;
    const int h    = warp & 1;
    const int e2   = (warp >> 1) & 1;
    const int ksw  = warp >> 2;
    const int g    = lane >> 2;
    const int tig  = lane & 3;
    const int t0   = blockIdx.x * TM;

    if (tid < NE) { sLoads[tid] = 0.f; sBias[tid] = g_bias[tid]; }

    const uint32_t smem32 = (uint32_t)__cvta_generic_to_shared(dsm);

    // X fill coords: flat float4 index f = u*256+tid -> row = f>>4, c4 = f&15
    const int frow0 = tid >> 4;      // + u*16
    const int fc4   = tid & 15;
    // X store byte offset pieces (within plane): row varies with u
    // B fill coords: f = u*256+tid -> row = f>>3, chunk = f&7

    float acc0[4][4][4], accS[4][4][4];
    #pragma unroll
    for (int i = 0; i < 4; i++)
        #pragma unroll
        for (int j = 0; j < 4; j++)
            #pragma unroll
            for (int q = 0; q < 4; q++) { acc0[i][j][q] = 0.f; accS[i][j][q] = 0.f; }

    float4 xr[8];

    // ---- fill chunk 0 into stage 0 ----
    {
        #pragma unroll
        for (int u = 0; u < 8; u++) {
            int row = u * 16 + frow0;
            xr[u] = *(const float4*)(X + (size_t)(t0 + row) * DIM + fc4 * 4);
        }
        #pragma unroll
        for (int u = 0; u < 8; u++) {
            int row = u * 16 + frow0;
            uint32_t h0, l0, h1, l1;
            split2(xr[u].x, xr[u].y, h0, l0);
            split2(xr[u].z, xr[u].w, h1, l1);
            uint32_t byte = (uint32_t)(SWZ(row, (fc4 >> 1)) + (fc4 & 1) * 8);
            *(uint2*)(dsm + AH_B + byte) = make_uint2(h0, h1);
            *(uint2*)(dsm + AL_B + byte) = make_uint2(l0, l1);
        }
        #pragma unroll
        for (int u = 0; u < 2; u++) {
            int f = u * 256 + tid;
            int row = f >> 3, cc = f & 7;
            uint32_t dst = smem32 + (uint32_t)SWZ(row, cc);
            cpa16(dst + BH_B, g_wh16 + (size_t)row * DIM + cc * 8);
            cpa16(dst + BL_B, g_wl16 + (size_t)row * DIM + cc * 8);
        }
        asm volatile("cp.async.commit_group;" ::: "memory");
        asm volatile("cp.async.wait_group 0;" ::: "memory");
    }
    __syncthreads();

    // ---- mainloop ----
    for (int c = 0; c < NCH; ++c) {
        const bool more = (c + 1 < NCH);
        if (more) {
            int kb = (c + 1) * KC;
            #pragma unroll
            for (int u = 0; u < 8; u++) {
                int row = u * 16 + frow0;
                xr[u] = *(const float4*)(X + (size_t)(t0 + row) * DIM + kb + fc4 * 4);
            }
            uint32_t sb = smem32 + (uint32_t)(((c + 1) & 1) * STG_B);
            #pragma unroll
            for (int u = 0; u < 2; u++) {
                int f = u * 256 + tid;
                int row = f >> 3, cc = f & 7;
                uint32_t dst = sb + (uint32_t)SWZ(row, cc);
                cpa16(dst + BH_B, g_wh16 + (size_t)row * DIM + kb + cc * 8);
                cpa16(dst + BL_B, g_wl16 + (size_t)row * DIM + kb + cc * 8);
            }
            asm volatile("cp.async.commit_group;" ::: "memory");
        }

        // ---- consume stage c&1 (conflict-free swizzled ldmatrix) ----
        {
            const uint32_t stg32 = smem32 + (uint32_t)((c & 1) * STG_B);
            // B rows fixed per lane
            const int rowB = 32 * e2 + ((lane >> 4) << 3) + (lane & 7);
            const uint32_t rowBb = (uint32_t)(rowB << 7);
            const int rxB = rowB & 7;
            const int laneA15 = lane & 15;
            const int kaSel = lane >> 4;           // A chunk select
            const int kbSel = (lane >> 3) & 1;     // B chunk select

            #pragma unroll
            for (int kk = 0; kk < 2; kk++) {
                const int kstep = ksw * 2 + kk;

                uint32_t Ah[4][4], Al[4][4];
                #pragma unroll
                for (int i = 0; i < 4; i++) {
                    int rowA = 64 * h + 16 * i + laneA15;
                    int kc = kstep * 2 + kaSel;
                    uint32_t a = stg32 + (uint32_t)((rowA << 7) + (((kc ^ (rowA & 7))) << 4));
                    ldsm4(Ah[i][0], Ah[i][1], Ah[i][2], Ah[i][3], a + AH_B);
                    ldsm4(Al[i][0], Al[i][1], Al[i][2], Al[i][3], a + AL_B);
                }
                #pragma unroll
                for (int jp = 0; jp < 2; jp++) {
                    int rowBj = rowB + 16 * jp;
                    int kc = kstep * 2 + kbSel;
                    uint32_t b = stg32 + (uint32_t)(((rowBj) << 7) + (((kc ^ (rowBj & 7))) << 4));
                    uint32_t Bh0, Bh1, Bh2, Bh3, Bl0, Bl1, Bl2, Bl3;
                    ldsm4(Bh0, Bh1, Bh2, Bh3, b + BH_B);
                    ldsm4(Bl0, Bl1, Bl2, Bl3, b + BL_B);
                    #pragma unroll
                    for (int i = 0; i < 4; i++) {
                        mma16f(acc0[i][2*jp],   Ah[i][0], Ah[i][1], Ah[i][2], Ah[i][3], Bh0, Bh1);
                        mma16f(accS[i][2*jp],   Ah[i][0], Ah[i][1], Ah[i][2], Ah[i][3], Bl0, Bl1);
                        mma16f(accS[i][2*jp],   Al[i][0], Al[i][1], Al[i][2], Al[i][3], Bh0, Bh1);
                        mma16f(acc0[i][2*jp+1], Ah[i][0], Ah[i][1], Ah[i][2], Ah[i][3], Bh2, Bh3);
                        mma16f(accS[i][2*jp+1], Ah[i][0], Ah[i][1], Ah[i][2], Ah[i][3], Bl2, Bl3);
                        mma16f(accS[i][2*jp+1], Al[i][0], Al[i][1], Al[i][2], Al[i][3], Bh2, Bh3);
                    }
                }
            }
            (void)rowBb; (void)rxB;
        }

        // ---- store X(c+1) + drain B cp.async ----
        if (more) {
            char* sd = dsm + ((c + 1) & 1) * STG_B;
            #pragma unroll
            for (int u = 0; u < 8; u++) {
                int row = u * 16 + frow0;
                uint32_t h0, l0, h1, l1;
                split2(xr[u].x, xr[u].y, h0, l0);
                split2(xr[u].z, xr[u].w, h1, l1);
                uint32_t byte = (uint32_t)(SWZ(row, (fc4 >> 1)) + (fc4 & 1) * 8);
                *(uint2*)(sd + AH_B + byte) = make_uint2(h0, h1);
                *(uint2*)(sd + AL_B + byte) = make_uint2(l0, l1);
            }
            asm volatile("cp.async.wait_group 0;" ::: "memory");
        }
        __syncthreads();
    }

    // ---- cross-kstep reduction into logits tile Ls[128][68] ----
    float* Ls = (float*)dsm;
    for (int idx = tid; idx < TM * LS_STRIDE; idx += NTH) Ls[idx] = 0.f;
    __syncthreads();

    for (int round = 0; round < 2; round++) {
        if (ksw == round) {
            #pragma unroll
            for (int i = 0; i < 4; i++) {
                int rt = 64 * h + 16 * i + g;
                #pragma unroll
                for (int j = 0; j < 4; j++) {
                    int cc = 32 * e2 + 8 * j + 2 * tig;
                    Ls[rt * LS_STRIDE + cc]           += acc0[i][j][0] + accS[i][j][0] * INV2048;
                    Ls[rt * LS_STRIDE + cc + 1]       += acc0[i][j][1] + accS[i][j][1] * INV2048;
                    Ls[(rt + 8) * LS_STRIDE + cc]     += acc0[i][j][2] + accS[i][j][2] * INV2048;
                    Ls[(rt + 8) * LS_STRIDE + cc + 1] += acc0[i][j][3] + accS[i][j][3] * INV2048;
                }
            }
        }
        __syncthreads();
    }

    // ---- epilogue: per-token top-8 + softmax + load scatter ----
    if (tid < TM) {
        const int t = tid;
        size_t gt = (size_t)(t0 + t);

        float nzf[NE];
        const float4* nr = (const float4*)(noise + gt * NE);
        #pragma unroll
        for (int i = 0; i < 16; i++) {
            float4 v = nr[i];
            nzf[4 * i + 0] = v.x; nzf[4 * i + 1] = v.y;
            nzf[4 * i + 2] = v.z; nzf[4 * i + 3] = v.w;
        }

        float tv[TK];
        int   ti_[TK];
        #pragma unroll
        for (int k = 0; k < TK; k++) { tv[k] = -INFINITY; ti_[k] = -1; }

        for (int e = 0; e < NE; e++) {
            float v = Ls[t * LS_STRIDE + e] + 0.01f * nzf[e] - sBias[e];
            if (v > tv[TK - 1]) {                 // strict >: earlier equal value stays
                int p = TK - 1;
                while (p > 0 && tv[p - 1] < v) {  // stop at equal -> stable insert
                    tv[p] = tv[p - 1];
                    ti_[p] = ti_[p - 1];
                    --p;
                }
                tv[p] = v;
                ti_[p] = e;
            }
        }

        float m = tv[0];
        float w[TK];
        float ssum = 0.f;
        #pragma unroll
        for (int k = 0; k < TK; k++) { w[k] = expf(tv[k] - m); ssum += w[k]; }
        float inv = 1.0f / ssum;

        size_t woff = (size_t)ntok * TK;
        #pragma unroll
        for (int k = 0; k < TK; k++) {
            float wk = w[k] * inv;
            out[gt * TK + k]        = (float)ti_[k];
            out[woff + gt * TK + k] = wk;
            atomicAdd(&sLoads[ti_[k]], wk);
        }
    }
    __syncthreads();
    if (tid < NE) atomicAdd(&g_acc[tid], sLoads[tid]);

    // ---- fused finalize: last CTA writes EMA + bias strength ----
    __threadfence();
    __syncthreads();
    if (tid == 0) {
        unsigned int n = atomicAdd(&g_done, 1u);
        sLast = (n == gridDim.x - 1) ? 1 : 0;
    }
    __syncthreads();
    if (sLast && tid < NE) {
        float batch = atomicAdd(&g_acc[tid], 0.0f) / (float)ntok;
        size_t bofs = (size_t)ntok * TK * 2;
        out[bofs + tid] = 0.999f * loads[tid] + (1.0f - 0.999f) * batch;
        if (tid == 0) { out[bofs + NE] = g_nbs; g_done = 0u; }
    }
}

// ---------------------------------------------------------------------------
// Launch
// ---------------------------------------------------------------------------
extern "C" void kernel_launch(void* const* d_in, const int* in_sizes, int n_in,
                              void* d_out, int out_size)
{
    const float* X     = (const float*)d_in[0];  // hidden_states [4,4096,2048]
    const float* W     = (const float*)d_in[1];  // router_w [64,2048]
    const float* loads = (const float*)d_in[2];  // expert_loads [64]
    const float* bs    = (const float*)d_in[3];  // bias_strength [1]
    const float* noise = (const float*)d_in[4];  // noise [16384,64]
    float* out = (float*)d_out;

    int ntok = in_sizes[0] / DIM;

    cudaFuncSetAttribute(k_router, cudaFuncAttributeMaxDynamicSharedMemorySize, DYN_BYTES);

    k_setup<<<NE + 1, 256>>>(W, loads, bs);
    k_router<<<ntok / TM, NTH, DYN_BYTES>>>(X, noise, loads, out, ntok);
}

// round 13
// speedup vs baseline: 1.8090x; 1.0198x over previous
#include <cuda_runtime.h>
#include <cuda_fp16.h>
#include <math.h>
#include <stdint.h>

#define NE   64
#define TK   8
#define DIM  2048
#define TM   128            // tokens per CTA
#define KC   64             // fp32 k per chunk (64 fp16 = 128B row)
#define NCH  (DIM / KC)     // 32 chunks
#define NTH  512
#define INV2048 (1.0f / 2048.0f)
#define LS_STRIDE 68

// stage byte layout: 128B rows, XOR-swizzled 16B chunks
#define AH_B 0
#define AL_B 16384
#define BH_B 32768
#define BL_B 40960
#define STG_B 49152
#define DYN_BYTES (2 * STG_B)    // 98304

__device__ __align__(16) uint16_t g_wh16[NE * DIM];   // W hi (fp16)
__device__ __align__(16) uint16_t g_wl16[NE * DIM];   // W lo (fp16, scaled 2^11)
__device__ __align__(16) float g_bias[NE];
__device__ float g_nbs;
__device__ float g_acc[NE];
__device__ unsigned int g_done;   // zero-init; reset by last CTA each run

// swizzled byte offset of 16B chunk (row, c) within a plane
#define SWZ(row, c) (((row) << 7) + ((((c) ^ ((row) & 7))) << 4))

// 2-term fp16 split of (x,y) -> packed hi fp16x2, lo fp16x2 (lo scaled 2^11)
static __device__ __forceinline__ void split2(float x, float y,
                                              uint32_t& hh, uint32_t& ll)
{
    __half2 a = __floats2half2_rn(x, y);
    float rx = (x - __half2float(__low2half(a))) * 2048.f;
    float ry = (y - __half2float(__high2half(a))) * 2048.f;
    __half2 l = __floats2half2_rn(rx, ry);
    hh = *(uint32_t*)&a;
    ll = *(uint32_t*)&l;
}

static __device__ __forceinline__ void mma16f(float* c,
    uint32_t a0, uint32_t a1, uint32_t a2, uint32_t a3, uint32_t b0, uint32_t b1)
{
    asm volatile(
        "mma.sync.aligned.m16n8k16.row.col.f32.f16.f16.f32 "
        "{%0,%1,%2,%3}, {%4,%5,%6,%7}, {%8,%9}, {%0,%1,%2,%3};"
        : "+f"(c[0]), "+f"(c[1]), "+f"(c[2]), "+f"(c[3])
        : "r"(a0), "r"(a1), "r"(a2), "r"(a3), "r"(b0), "r"(b1));
}

static __device__ __forceinline__ void ldsm4(uint32_t& r0, uint32_t& r1,
                                             uint32_t& r2, uint32_t& r3, uint32_t a)
{
    asm volatile("ldmatrix.sync.aligned.m8n8.x4.shared.b16 {%0,%1,%2,%3}, [%4];"
                 : "=r"(r0), "=r"(r1), "=r"(r2), "=r"(r3) : "r"(a));
}

static __device__ __forceinline__ void cpa16(uint32_t dst, const void* src) {
    asm volatile("cp.async.ca.shared.global [%0], [%1], 16;"
                 :: "r"(dst), "l"(src) : "memory");
}

// ---------------------------------------------------------------------------
// Setup: split W into fp16 hi/lo planes (blocks 0..63), bias (block 64)
// ---------------------------------------------------------------------------
__global__ void k_setup(const float* __restrict__ W,
                        const float* __restrict__ loads,
                        const float* __restrict__ bs)
{
    int b = blockIdx.x, tid = threadIdx.x;

    if (b < NE) {
        const float2* wr = (const float2*)(W + (size_t)b * DIM);
        uint32_t* wh = (uint32_t*)g_wh16;
        uint32_t* wl = (uint32_t*)g_wl16;
        #pragma unroll
        for (int u = 0; u < 4; u++) {
            int f = u * 256 + tid;
            float2 v = wr[f];
            uint32_t hh, ll;
            split2(v.x, v.y, hh, ll);
            int idx = b * (DIM / 2) + f;
            wh[idx] = hh;
            wl[idx] = ll;
        }
    } else {
        __shared__ float s[NE], s2[NE];
        if (tid < NE) s[tid] = loads[tid];
        __syncthreads();
        float sum = 0.f, q = 0.f;
        const float t = 1.0f / (float)NE;
        if (tid < NE) {
            #pragma unroll
            for (int i = 0; i < NE; i++) sum += s[i];
            sum = fmaxf(sum, 1e-8f);
            q = s[tid] / sum;
            s2[tid] = t * (logf(t) - logf(fmaxf(q, 1e-8f)));
        }
        __syncthreads();
        if (tid < NE) {
            float kl = 0.f;
            #pragma unroll
            for (int i = 0; i < NE; i++) kl += s2[i];
            float adaptive = 1.0f / (1.0f + expf(-10.0f * kl));
            float nbs = 0.9f * bs[0] + 0.1f * adaptive;
            g_bias[tid] = tanhf((q - t) * (float)NE) * nbs;
            g_acc[tid] = 0.f;
            if (tid == 0) g_nbs = nbs;
        }
    }
}

// ---------------------------------------------------------------------------
// Router: fp16 2-term / 3-product mma16 GEMM, swizzled staging, 16 warps
// warp w (0..15): h2 = w&3 token quarter, e2 = (w>>2)&1 expert half, ksw = w>>3
// ---------------------------------------------------------------------------
__global__ __launch_bounds__(NTH, 1) void k_router(
    const float* __restrict__ X,      // [ntok, DIM]
    const float* __restrict__ noise,  // [ntok, NE]
    const float* __restrict__ loads,  // [NE]
    float* __restrict__ out,
    int ntok)
{
    extern __shared__ __align__(16) char dsm[];
    __shared__ float sLoads[NE];
    __shared__ float sBias[NE];
    __shared__ int sLast;

    const int tid  = threadIdx.x;
    const int lane = tid & 31;
    const int warp = tid >> 5;
    const int h2   = warp & 3;        // token quarter (32 tokens)
    const int e2   = (warp >> 2) & 1; // expert half
    const int ksw  = warp >> 3;       // k32 half of chunk
    const int g    = lane >> 2;
    const int tig  = lane & 3;
    const int t0   = blockIdx.x * TM;

    if (tid < NE) { sLoads[tid] = 0.f; sBias[tid] = g_bias[tid]; }

    const uint32_t smem32 = (uint32_t)__cvta_generic_to_shared(dsm);

    // X fill coords: flat float4 index f = u*512+tid -> row = f>>4, c4 = f&15
    const int frow0 = tid >> 4;      // 0..31, + u*32
    const int fc4   = tid & 15;
    // B fill coords: f = tid -> row = tid>>3, chunk = tid&7 (one pass covers 64x8)
    const int brow = tid >> 3;
    const int bcc  = tid & 7;

    float acc0[2][4][4], accS[2][4][4];
    #pragma unroll
    for (int i = 0; i < 2; i++)
        #pragma unroll
        for (int j = 0; j < 4; j++)
            #pragma unroll
            for (int q = 0; q < 4; q++) { acc0[i][j][q] = 0.f; accS[i][j][q] = 0.f; }

    float4 xr[4];

    // ---- fill chunk 0 into stage 0 ----
    {
        #pragma unroll
        for (int u = 0; u < 4; u++) {
            int row = u * 32 + frow0;
            xr[u] = *(const float4*)(X + (size_t)(t0 + row) * DIM + fc4 * 4);
        }
        #pragma unroll
        for (int u = 0; u < 4; u++) {
            int row = u * 32 + frow0;
            uint32_t h0, l0, h1, l1;
            split2(xr[u].x, xr[u].y, h0, l0);
            split2(xr[u].z, xr[u].w, h1, l1);
            uint32_t byte = (uint32_t)(SWZ(row, (fc4 >> 1)) + (fc4 & 1) * 8);
            *(uint2*)(dsm + AH_B + byte) = make_uint2(h0, h1);
            *(uint2*)(dsm + AL_B + byte) = make_uint2(l0, l1);
        }
        {
            uint32_t dst = smem32 + (uint32_t)SWZ(brow, bcc);
            cpa16(dst + BH_B, g_wh16 + (size_t)brow * DIM + bcc * 8);
            cpa16(dst + BL_B, g_wl16 + (size_t)brow * DIM + bcc * 8);
        }
        asm volatile("cp.async.commit_group;" ::: "memory");
        asm volatile("cp.async.wait_group 0;" ::: "memory");
    }
    __syncthreads();

    // ---- mainloop ----
    for (int c = 0; c < NCH; ++c) {
        const bool more = (c + 1 < NCH);
        if (more) {
            int kb = (c + 1) * KC;
            #pragma unroll
            for (int u = 0; u < 4; u++) {
                int row = u * 32 + frow0;
                xr[u] = *(const float4*)(X + (size_t)(t0 + row) * DIM + kb + fc4 * 4);
            }
            uint32_t sb = smem32 + (uint32_t)(((c + 1) & 1) * STG_B);
            uint32_t dst = sb + (uint32_t)SWZ(brow, bcc);
            cpa16(dst + BH_B, g_wh16 + (size_t)brow * DIM + kb + bcc * 8);
            cpa16(dst + BL_B, g_wl16 + (size_t)brow * DIM + kb + bcc * 8);
            asm volatile("cp.async.commit_group;" ::: "memory");
        }

        // ---- consume stage c&1 (conflict-free swizzled ldmatrix) ----
        {
            const uint32_t stg32 = smem32 + (uint32_t)((c & 1) * STG_B);
            const int rowB = 32 * e2 + ((lane >> 4) << 3) + (lane & 7);
            const int laneA15 = lane & 15;
            const int kaSel = lane >> 4;           // A chunk select
            const int kbSel = (lane >> 3) & 1;     // B chunk select

            #pragma unroll
            for (int kk = 0; kk < 2; kk++) {
                const int kstep = ksw * 2 + kk;

                uint32_t Ah[2][4], Al[2][4];
                #pragma unroll
                for (int i = 0; i < 2; i++) {
                    int rowA = 32 * h2 + 16 * i + laneA15;
                    int kc = kstep * 2 + kaSel;
                    uint32_t a = stg32 + (uint32_t)((rowA << 7) + (((kc ^ (rowA & 7))) << 4));
                    ldsm4(Ah[i][0], Ah[i][1], Ah[i][2], Ah[i][3], a + AH_B);
                    ldsm4(Al[i][0], Al[i][1], Al[i][2], Al[i][3], a + AL_B);
                }
                #pragma unroll
                for (int jp = 0; jp < 2; jp++) {
                    int rowBj = rowB + 16 * jp;
                    int kc = kstep * 2 + kbSel;
                    uint32_t b = stg32 + (uint32_t)(((rowBj) << 7) + (((kc ^ (rowBj & 7))) << 4));
                    uint32_t Bh0, Bh1, Bh2, Bh3, Bl0, Bl1, Bl2, Bl3;
                    ldsm4(Bh0, Bh1, Bh2, Bh3, b + BH_B);
                    ldsm4(Bl0, Bl1, Bl2, Bl3, b + BL_B);
                    #pragma unroll
                    for (int i = 0; i < 2; i++) {
                        mma16f(acc0[i][2*jp],   Ah[i][0], Ah[i][1], Ah[i][2], Ah[i][3], Bh0, Bh1);
                        mma16f(accS[i][2*jp],   Ah[i][0], Ah[i][1], Ah[i][2], Ah[i][3], Bl0, Bl1);
                        mma16f(accS[i][2*jp],   Al[i][0], Al[i][1], Al[i][2], Al[i][3], Bh0, Bh1);
                        mma16f(acc0[i][2*jp+1], Ah[i][0], Ah[i][1], Ah[i][2], Ah[i][3], Bh2, Bh3);
                        mma16f(accS[i][2*jp+1], Ah[i][0], Ah[i][1], Ah[i][2], Ah[i][3], Bl2, Bl3);
                        mma16f(accS[i][2*jp+1], Al[i][0], Al[i][1], Al[i][2], Al[i][3], Bh2, Bh3);
                    }
                }
            }
        }

        // ---- store X(c+1) + drain B cp.async ----
        if (more) {
            char* sd = dsm + ((c + 1) & 1) * STG_B;
            #pragma unroll
            for (int u = 0; u < 4; u++) {
                int row = u * 32 + frow0;
                uint32_t h0, l0, h1, l1;
                split2(xr[u].x, xr[u].y, h0, l0);
                split2(xr[u].z, xr[u].w, h1, l1);
                uint32_t byte = (uint32_t)(SWZ(row, (fc4 >> 1)) + (fc4 & 1) * 8);
                *(uint2*)(sd + AH_B + byte) = make_uint2(h0, h1);
                *(uint2*)(sd + AL_B + byte) = make_uint2(l0, l1);
            }
            asm volatile("cp.async.wait_group 0;" ::: "memory");
        }
        __syncthreads();
    }

    // ---- cross-kstep reduction into logits tile Ls[128][68] ----
    float* Ls = (float*)dsm;
    for (int idx = tid; idx < TM * LS_STRIDE; idx += NTH) Ls[idx] = 0.f;
    __syncthreads();

    for (int round = 0; round < 2; round++) {
        if (ksw == round) {
            #pragma unroll
            for (int i = 0; i < 2; i++) {
                int rt = 32 * h2 + 16 * i + g;
                #pragma unroll
                for (int j = 0; j < 4; j++) {
                    int cc = 32 * e2 + 8 * j + 2 * tig;
                    Ls[rt * LS_STRIDE + cc]           += acc0[i][j][0] + accS[i][j][0] * INV2048;
                    Ls[rt * LS_STRIDE + cc + 1]       += acc0[i][j][1] + accS[i][j][1] * INV2048;
                    Ls[(rt + 8) * LS_STRIDE + cc]     += acc0[i][j][2] + accS[i][j][2] * INV2048;
                    Ls[(rt + 8) * LS_STRIDE + cc + 1] += acc0[i][j][3] + accS[i][j][3] * INV2048;
                }
            }
        }
        __syncthreads();
    }

    // ---- epilogue: per-token top-8 + softmax + load scatter ----
    if (tid < TM) {
        const int t = tid;
        size_t gt = (size_t)(t0 + t);

        float nzf[NE];
        const float4* nr = (const float4*)(noise + gt * NE);
        #pragma unroll
        for (int i = 0; i < 16; i++) {
            float4 v = nr[i];
            nzf[4 * i + 0] = v.x; nzf[4 * i + 1] = v.y;
            nzf[4 * i + 2] = v.z; nzf[4 * i + 3] = v.w;
        }

        float tv[TK];
        int   ti_[TK];
        #pragma unroll
        for (int k = 0; k < TK; k++) { tv[k] = -INFINITY; ti_[k] = -1; }

        for (int e = 0; e < NE; e++) {
            float v = Ls[t * LS_STRIDE + e] + 0.01f * nzf[e] - sBias[e];
            if (v > tv[TK - 1]) {                 // strict >: earlier equal value stays
                int p = TK - 1;
                while (p > 0 && tv[p - 1] < v) {  // stop at equal -> stable insert
                    tv[p] = tv[p - 1];
                    ti_[p] = ti_[p - 1];
                    --p;
                }
                tv[p] = v;
                ti_[p] = e;
            }
        }

        float m = tv[0];
        float w[TK];
        float ssum = 0.f;
        #pragma unroll
        for (int k = 0; k < TK; k++) { w[k] = expf(tv[k] - m); ssum += w[k]; }
        float inv = 1.0f / ssum;

        size_t woff = (size_t)ntok * TK;
        #pragma unroll
        for (int k = 0; k < TK; k++) {
            float wk = w[k] * inv;
            out[gt * TK + k]        = (float)ti_[k];
            out[woff + gt * TK + k] = wk;
            atomicAdd(&sLoads[ti_[k]], wk);
        }
    }
    __syncthreads();
    if (tid < NE) atomicAdd(&g_acc[tid], sLoads[tid]);

    // ---- fused finalize: last CTA writes EMA + bias strength ----
    __threadfence();
    __syncthreads();
    if (tid == 0) {
        unsigned int n = atomicAdd(&g_done, 1u);
        sLast = (n == gridDim.x - 1) ? 1 : 0;
    }
    __syncthreads();
    if (sLast && tid < NE) {
        float batch = atomicAdd(&g_acc[tid], 0.0f) / (float)ntok;
        size_t bofs = (size_t)ntok * TK * 2;
        out[bofs + tid] = 0.999f * loads[tid] + (1.0f - 0.999f) * batch;
        if (tid == 0) { out[bofs + NE] = g_nbs; g_done = 0u; }
    }
}

// ---------------------------------------------------------------------------
// Launch
// ---------------------------------------------------------------------------
extern "C" void kernel_launch(void* const* d_in, const int* in_sizes, int n_in,
                              void* d_out, int out_size)
{
    const float* X     = (const float*)d_in[0];  // hidden_states [4,4096,2048]
    const float* W     = (const float*)d_in[1];  // router_w [64,2048]
    const float* loads = (const float*)d_in[2];  // expert_loads [64]
    const float* bs    = (const float*)d_in[3];  // bias_strength [1]
    const float* noise = (const float*)d_in[4];  // noise [16384,64]
    float* out = (float*)d_out;

    int ntok = in_sizes[0] / DIM;

    cudaFuncSetAttribute(k_router, cudaFuncAttributeMaxDynamicSharedMemorySize, DYN_BYTES);

    k_setup<<<NE + 1, 256>>>(W, loads, bs);
    k_router<<<ntok / TM, NTH, DYN_BYTES>>>(X, noise, loads, out, ntok);
}